// round 10
// baseline (speedup 1.0000x reference)
#include <cuda_runtime.h>
#include <cuda.h>
#include <cstdint>

// LIF neuron scan — warp-autonomous pipelines with wide units.
// 64 CTAs x 128 threads; each warp owns one unit of 128 contiguous neurons
// (thread = 4 neurons, float4). Private 4-stage TMA ring per warp, no
// intra-CTA synchronization in the main loop. Stores are STG.128 (512 B
// contiguous per warp per stream per step) for DRAM row locality.
//
// Inputs : d_in[0] = input_current  f32 [B=32, T=1000, N=1024]
//          d_in[1] = v_init         f32 [B=32, N=1024]
// Output : d_out = [2, B, T, N] f32  (spikes block, then voltages block)
//
// Recurrence:
//   v = v + (i - v) / 10.0     (correctly-rounded div via Markstein FMA seq)
//   s = (v >= 1.0) ? 1 : 0
//   v = s ? 0 : v

#define LIF_B   32
#define LIF_T   1000
#define LIF_N   1024
#define TC      20                     // timesteps per chunk
#define NSTAGE  4                      // per-warp pipeline depth
#define NWARP   4                      // warps per CTA
#define NTHREAD (NWARP * 32)           // 128 threads
#define NCHUNK  (LIF_T / TC)           // 50
#define UNIT_N  128                    // neurons per warp
#define UNIT_BYTES (TC * UNIT_N * 4)   // 10240 per unit per chunk
#define NCTA    64                     // 256 units / 4 warps

struct LifSmem {
    float tile[NWARP][NSTAGE][TC][UNIT_N];   // 4*4*20*128*4 = 163840 B
    unsigned long long mbar[NWARP][NSTAGE];
};

static __device__ __forceinline__ unsigned smem_u32(const void* p) {
    return (unsigned)__cvta_generic_to_shared(p);
}

static __device__ __forceinline__ void mbar_init(unsigned mbar, unsigned count) {
    asm volatile("mbarrier.init.shared.b64 [%0], %1;" :: "r"(mbar), "r"(count) : "memory");
}

static __device__ __forceinline__ void mbar_expect_tx(unsigned mbar, unsigned bytes) {
    asm volatile("mbarrier.arrive.expect_tx.shared.b64 _, [%0], %1;"
                 :: "r"(mbar), "r"(bytes) : "memory");
}

static __device__ __forceinline__ void mbar_wait(unsigned mbar, unsigned parity) {
    asm volatile(
        "{\n\t"
        ".reg .pred P1;\n\t"
        "LAB_WAIT_%=:\n\t"
        "mbarrier.try_wait.parity.acquire.cta.shared::cta.b64 P1, [%0], %1, 0x989680;\n\t"
        "@P1 bra LAB_DONE_%=;\n\t"
        "bra LAB_WAIT_%=;\n\t"
        "LAB_DONE_%=:\n\t"
        "}"
        :: "r"(mbar), "r"(parity) : "memory");
}

static __device__ __forceinline__ void tma_load_box(unsigned dst_smem,
                                                    const CUtensorMap* map,
                                                    int x, int y, int z,
                                                    unsigned mbar) {
    asm volatile(
        "cp.async.bulk.tensor.3d.shared::cta.global.tile.mbarrier::complete_tx::bytes "
        "[%0], [%1, {%2, %3, %4}], [%5];"
        :: "r"(dst_smem), "l"(map), "r"(x), "r"(y), "r"(z), "r"(mbar) : "memory");
}

static __device__ __forceinline__ float lif_step(float v, float i, float& s_out) {
    float x  = i - v;                  // (-(v - 0) + i)
    float q0 = x * 0.1f;               // Markstein: correctly-rounded x/10
    float e  = fmaf(-10.0f, q0, x);
    float q  = fmaf(e, 0.1f, q0);
    v = v + q;
    s_out = (v >= 1.0f) ? 1.0f : 0.0f;
    return (v >= 1.0f) ? 0.0f : v;
}

static __global__ __launch_bounds__(NTHREAD)
void lif_scan_kernel(const __grid_constant__ CUtensorMap tmap,
                     const float* __restrict__ v0,
                     float* __restrict__ out)
{
    extern __shared__ char smem_raw[];
    LifSmem* sm = reinterpret_cast<LifSmem*>(smem_raw);

    const int tid  = threadIdx.x;
    const int lane = tid & 31;
    const int w    = tid >> 5;                 // warp id in CTA

    // Unit assignment: unit = bid*4 + w, 256 units total, perfect balance.
    const int u  = blockIdx.x * NWARP + w;
    const int b  = u >> 3;                     // batch (8 units per batch)
    const int un = (u & 7) * UNIT_N;           // first neuron of this unit
    const int n  = un + lane * 4;              // this thread's first neuron

    if (tid == 0) {
        for (int q = 0; q < NWARP; ++q)
            for (int i = 0; i < NSTAGE; ++i)
                mbar_init(smem_u32(&sm->mbar[q][i]), 1);
        asm volatile("fence.proxy.async.shared::cta;" ::: "memory");
    }
    __syncthreads();   // only CTA sync: mbar init visibility

    // Prologue: this warp fills its own stages (lane 0 issues).
    if (lane == 0) {
        #pragma unroll
        for (int c = 0; c < NSTAGE; ++c) {
            const unsigned mb = smem_u32(&sm->mbar[w][c]);
            mbar_expect_tx(mb, UNIT_BYTES);
            tma_load_box(smem_u32(&sm->tile[w][c][0][0]), &tmap,
                         un, c * TC, b, mb);
        }
    }

    // Per-thread state: 4 neurons.
    float4 v = *(const float4*)(v0 + (long long)b * LIF_N + n);

    float* sp = out + (long long)b * (LIF_T * LIF_N) + n;          // spikes
    float* vp = sp + (long long)LIF_B * LIF_T * LIF_N;             // voltages

    #pragma unroll 1
    for (int c = 0; c < NCHUNK; ++c) {
        const int s = c & (NSTAGE - 1);
        const unsigned parity = (c >> 2) & 1;

        mbar_wait(smem_u32(&sm->mbar[w][s]), parity);

        #pragma unroll
        for (int r = 0; r < TC; ++r) {
            float4 cur = ((const float4*)&sm->tile[w][s][r][0])[lane];
            float4 spk;
            v.x = lif_step(v.x, cur.x, spk.x);
            v.y = lif_step(v.y, cur.y, spk.y);
            v.z = lif_step(v.z, cur.z, spk.z);
            v.w = lif_step(v.w, cur.w, spk.w);
            const long long off = (long long)(c * TC + r) * LIF_N;
            __stcs((float4*)(sp + off), spk);
            __stcs((float4*)(vp + off), v);
        }

        // Sole consumer of its tiles; all reads above are consumed (stores
        // depend on them), so refilling stage s is safe without a sync.
        if (lane == 0 && c + NSTAGE < NCHUNK) {
            const unsigned mb = smem_u32(&sm->mbar[w][s]);
            mbar_expect_tx(mb, UNIT_BYTES);
            tma_load_box(smem_u32(&sm->tile[w][s][0][0]), &tmap,
                         un, (c + NSTAGE) * TC, b, mb);
        }
    }
}

typedef CUresult (*EncodeTiledFn)(
    CUtensorMap*, CUtensorMapDataType, cuuint32_t, void*,
    const cuuint64_t*, const cuuint64_t*, const cuuint32_t*, const cuuint32_t*,
    CUtensorMapInterleave, CUtensorMapSwizzle, CUtensorMapL2promotion,
    CUtensorMapFloatOOBfill);

extern "C" void kernel_launch(void* const* d_in, const int* in_sizes, int n_in,
                              void* d_out, int out_size)
{
    const float* in = (const float*)d_in[0];   // [B, T, N]
    const float* v0 = (const float*)d_in[1];   // [B, N]
    float* out = (float*)d_out;                // [2, B, T, N]

    (void)in_sizes; (void)n_in; (void)out_size;

    // Fetch cuTensorMapEncodeTiled through the runtime (no -lcuda needed).
    void* fn_ptr = nullptr;
    cudaDriverEntryPointQueryResult qres;
    cudaGetDriverEntryPointByVersion("cuTensorMapEncodeTiled", &fn_ptr, 12000,
                                     cudaEnableDefault, &qres);
    EncodeTiledFn encode = (EncodeTiledFn)fn_ptr;

    // 3D map over input_current: dim0=N (contiguous), dim1=T, dim2=B.
    CUtensorMap tmap;
    cuuint64_t dims[3]    = {LIF_N, LIF_T, LIF_B};
    cuuint64_t strides[2] = {(cuuint64_t)LIF_N * 4,
                             (cuuint64_t)LIF_T * LIF_N * 4};
    cuuint32_t box[3]     = {UNIT_N, TC, 1};
    cuuint32_t estr[3]    = {1, 1, 1};
    encode(&tmap, CU_TENSOR_MAP_DATA_TYPE_FLOAT32, 3, (void*)in,
           dims, strides, box, estr,
           CU_TENSOR_MAP_INTERLEAVE_NONE, CU_TENSOR_MAP_SWIZZLE_NONE,
           CU_TENSOR_MAP_L2_PROMOTION_L2_128B, CU_TENSOR_MAP_FLOAT_OOB_FILL_NONE);

    const int smem_bytes = (int)sizeof(LifSmem);   // 160 KB -> 1 CTA/SM
    cudaFuncSetAttribute(lif_scan_kernel,
                         cudaFuncAttributeMaxDynamicSharedMemorySize, smem_bytes);

    lif_scan_kernel<<<NCTA, NTHREAD, smem_bytes>>>(tmap, v0, out);
}

// round 11
// speedup vs baseline: 1.1776x; 1.1776x over previous
#include <cuda_runtime.h>
#include <cuda.h>
#include <cstdint>

// LIF neuron scan — wide warp-autonomous pipelines, full SM coverage.
// 128 CTAs x 64 threads (2 warps); each warp owns one unit of 128 contiguous
// neurons (thread = 4 neurons, float4 => STG.128, 512 B bursts per stream per
// step). Private 8-stage TMA ring per warp, no intra-CTA sync in main loop.
//
// Inputs : d_in[0] = input_current  f32 [B=32, T=1000, N=1024]
//          d_in[1] = v_init         f32 [B=32, N=1024]
// Output : d_out = [2, B, T, N] f32  (spikes block, then voltages block)
//
// Recurrence:
//   v = v + (i - v) / 10.0     (correctly-rounded div via Markstein FMA seq)
//   s = (v >= 1.0) ? 1 : 0
//   v = s ? 0 : v

#define LIF_B   32
#define LIF_T   1000
#define LIF_N   1024
#define TC      20                     // timesteps per chunk
#define NSTAGE  8                      // per-warp pipeline depth
#define NWARP   2                      // warps per CTA
#define NTHREAD (NWARP * 32)           // 64 threads
#define NCHUNK  (LIF_T / TC)           // 50
#define UNIT_N  128                    // neurons per warp
#define UNIT_BYTES (TC * UNIT_N * 4)   // 10240 per unit per chunk
#define NCTA    128                    // 256 units / 2 warps

struct LifSmem {
    float tile[NWARP][NSTAGE][TC][UNIT_N];   // 2*8*20*128*4 = 163840 B
    unsigned long long mbar[NWARP][NSTAGE];
};

static __device__ __forceinline__ unsigned smem_u32(const void* p) {
    return (unsigned)__cvta_generic_to_shared(p);
}

static __device__ __forceinline__ void mbar_init(unsigned mbar, unsigned count) {
    asm volatile("mbarrier.init.shared.b64 [%0], %1;" :: "r"(mbar), "r"(count) : "memory");
}

static __device__ __forceinline__ void mbar_expect_tx(unsigned mbar, unsigned bytes) {
    asm volatile("mbarrier.arrive.expect_tx.shared.b64 _, [%0], %1;"
                 :: "r"(mbar), "r"(bytes) : "memory");
}

static __device__ __forceinline__ void mbar_wait(unsigned mbar, unsigned parity) {
    asm volatile(
        "{\n\t"
        ".reg .pred P1;\n\t"
        "LAB_WAIT_%=:\n\t"
        "mbarrier.try_wait.parity.acquire.cta.shared::cta.b64 P1, [%0], %1, 0x989680;\n\t"
        "@P1 bra LAB_DONE_%=;\n\t"
        "bra LAB_WAIT_%=;\n\t"
        "LAB_DONE_%=:\n\t"
        "}"
        :: "r"(mbar), "r"(parity) : "memory");
}

static __device__ __forceinline__ void tma_load_box(unsigned dst_smem,
                                                    const CUtensorMap* map,
                                                    int x, int y, int z,
                                                    unsigned mbar) {
    asm volatile(
        "cp.async.bulk.tensor.3d.shared::cta.global.tile.mbarrier::complete_tx::bytes "
        "[%0], [%1, {%2, %3, %4}], [%5];"
        :: "r"(dst_smem), "l"(map), "r"(x), "r"(y), "r"(z), "r"(mbar) : "memory");
}

static __device__ __forceinline__ float lif_step(float v, float i, float& s_out) {
    float x  = i - v;                  // (-(v - 0) + i)
    float q0 = x * 0.1f;               // Markstein: correctly-rounded x/10
    float e  = fmaf(-10.0f, q0, x);
    float q  = fmaf(e, 0.1f, q0);
    v = v + q;
    s_out = (v >= 1.0f) ? 1.0f : 0.0f;
    return (v >= 1.0f) ? 0.0f : v;
}

static __global__ __launch_bounds__(NTHREAD)
void lif_scan_kernel(const __grid_constant__ CUtensorMap tmap,
                     const float* __restrict__ v0,
                     float* __restrict__ out)
{
    extern __shared__ char smem_raw[];
    LifSmem* sm = reinterpret_cast<LifSmem*>(smem_raw);

    const int tid  = threadIdx.x;
    const int lane = tid & 31;
    const int w    = tid >> 5;                 // warp id in CTA

    // Unit assignment: unit = bid*2 + w, 256 units, perfect balance.
    const int u  = blockIdx.x * NWARP + w;
    const int b  = u >> 3;                     // batch (8 units per batch)
    const int un = (u & 7) * UNIT_N;           // first neuron of this unit
    const int n  = un + lane * 4;              // this thread's first neuron

    if (tid == 0) {
        for (int q = 0; q < NWARP; ++q)
            for (int i = 0; i < NSTAGE; ++i)
                mbar_init(smem_u32(&sm->mbar[q][i]), 1);
        asm volatile("fence.proxy.async.shared::cta;" ::: "memory");
    }
    __syncthreads();   // only CTA sync: mbar init visibility

    // Prologue: this warp fills its own stages (lane 0 issues).
    if (lane == 0) {
        #pragma unroll
        for (int c = 0; c < NSTAGE; ++c) {
            const unsigned mb = smem_u32(&sm->mbar[w][c]);
            mbar_expect_tx(mb, UNIT_BYTES);
            tma_load_box(smem_u32(&sm->tile[w][c][0][0]), &tmap,
                         un, c * TC, b, mb);
        }
    }

    // Per-thread state: 4 neurons.
    float4 v = *(const float4*)(v0 + (long long)b * LIF_N + n);

    float* sp = out + (long long)b * (LIF_T * LIF_N) + n;          // spikes
    float* vp = sp + (long long)LIF_B * LIF_T * LIF_N;             // voltages

    #pragma unroll 1
    for (int c = 0; c < NCHUNK; ++c) {
        const int s = c & (NSTAGE - 1);
        const unsigned parity = (c >> 3) & 1;

        mbar_wait(smem_u32(&sm->mbar[w][s]), parity);

        #pragma unroll
        for (int r = 0; r < TC; ++r) {
            float4 cur = ((const float4*)&sm->tile[w][s][r][0])[lane];
            float4 spk;
            v.x = lif_step(v.x, cur.x, spk.x);
            v.y = lif_step(v.y, cur.y, spk.y);
            v.z = lif_step(v.z, cur.z, spk.z);
            v.w = lif_step(v.w, cur.w, spk.w);
            const long long off = (long long)(c * TC + r) * LIF_N;
            __stcs((float4*)(sp + off), spk);
            __stcs((float4*)(vp + off), v);
        }

        // Sole consumer of its tiles; reads above are all consumed (the
        // stores depend on them), so refilling stage s needs no sync.
        if (lane == 0 && c + NSTAGE < NCHUNK) {
            const unsigned mb = smem_u32(&sm->mbar[w][s]);
            mbar_expect_tx(mb, UNIT_BYTES);
            tma_load_box(smem_u32(&sm->tile[w][s][0][0]), &tmap,
                         un, (c + NSTAGE) * TC, b, mb);
        }
    }
}

typedef CUresult (*EncodeTiledFn)(
    CUtensorMap*, CUtensorMapDataType, cuuint32_t, void*,
    const cuuint64_t*, const cuuint64_t*, const cuuint32_t*, const cuuint32_t*,
    CUtensorMapInterleave, CUtensorMapSwizzle, CUtensorMapL2promotion,
    CUtensorMapFloatOOBfill);

extern "C" void kernel_launch(void* const* d_in, const int* in_sizes, int n_in,
                              void* d_out, int out_size)
{
    const float* in = (const float*)d_in[0];   // [B, T, N]
    const float* v0 = (const float*)d_in[1];   // [B, N]
    float* out = (float*)d_out;                // [2, B, T, N]

    (void)in_sizes; (void)n_in; (void)out_size;

    // Fetch cuTensorMapEncodeTiled through the runtime (no -lcuda needed).
    void* fn_ptr = nullptr;
    cudaDriverEntryPointQueryResult qres;
    cudaGetDriverEntryPointByVersion("cuTensorMapEncodeTiled", &fn_ptr, 12000,
                                     cudaEnableDefault, &qres);
    EncodeTiledFn encode = (EncodeTiledFn)fn_ptr;

    // 3D map over input_current: dim0=N (contiguous), dim1=T, dim2=B.
    CUtensorMap tmap;
    cuuint64_t dims[3]    = {LIF_N, LIF_T, LIF_B};
    cuuint64_t strides[2] = {(cuuint64_t)LIF_N * 4,
                             (cuuint64_t)LIF_T * LIF_N * 4};
    cuuint32_t box[3]     = {UNIT_N, TC, 1};
    cuuint32_t estr[3]    = {1, 1, 1};
    encode(&tmap, CU_TENSOR_MAP_DATA_TYPE_FLOAT32, 3, (void*)in,
           dims, strides, box, estr,
           CU_TENSOR_MAP_INTERLEAVE_NONE, CU_TENSOR_MAP_SWIZZLE_NONE,
           CU_TENSOR_MAP_L2_PROMOTION_L2_128B, CU_TENSOR_MAP_FLOAT_OOB_FILL_NONE);

    const int smem_bytes = (int)sizeof(LifSmem);   // 160 KB -> 1 CTA/SM
    cudaFuncSetAttribute(lif_scan_kernel,
                         cudaFuncAttributeMaxDynamicSharedMemorySize, smem_bytes);

    lif_scan_kernel<<<NCTA, NTHREAD, smem_bytes>>>(tmap, v0, out);
}